// round 1
// baseline (speedup 1.0000x reference)
#include <cuda_runtime.h>

#define NN 50000
#define NE 800000
#define IN_F 128
#define OUT_F 16
#define HEADS 4
#define HF 64          // HEADS*OUT_F
#define RB 256         // rows per GEMM block
#define KC 32          // k chunk

// ---- scratch (static device globals; allocation-free) ----
__device__ __align__(16) float g_h[NN * HF];          // 12.8 MB
__device__ __align__(16) float g_ssrc[NN * HEADS];    // 800 KB
__device__ __align__(16) float g_stgt[NN * HEADS];    // 800 KB
__device__ float g_denom[NN * HEADS];                 // 800 KB
__device__ float g_gmax;

__device__ __forceinline__ void atomicMaxFloat(float* addr, float val) {
    int old = __float_as_int(*addr);
    while (__int_as_float(old) < val) {
        int prev = atomicCAS((int*)addr, old, __float_as_int(val));
        if (prev == old) break;
        old = prev;
    }
}

// ---- K0: reset per-call state ----
__global__ void k_init(int n) {
    int i = blockIdx.x * blockDim.x + threadIdx.x;
    if (i < n * HEADS) g_denom[i] = 0.0f;
    if (i == 0) g_gmax = __int_as_float(0xff800000);  // -inf
}

// ---- K1: h = x @ W  (+ fused s_src / s_tgt epilogue) ----
// 256 threads, 256 rows/block. thread = (rq = tid>>2: 4-row group, head = tid&3).
// Each thread: 4 rows x 16 cols (one head) = 16 float4 accumulators.
__global__ __launch_bounds__(256) void k_gemm(
    const float* __restrict__ x, const float* __restrict__ W,
    const float* __restrict__ a_src, const float* __restrict__ a_tgt, int n)
{
    __shared__ float xs[RB * (KC + 1)];   // padded: stride 33 -> conflict-free
    __shared__ float4 Wc[KC * 16];        // W chunk as [k][16] float4

    const int tid = threadIdx.x;
    const int base = blockIdx.x * RB;
    const int rq = tid >> 2;
    const int head = tid & 3;

    float4 acc[4][4];
#pragma unroll
    for (int a = 0; a < 4; a++)
#pragma unroll
        for (int b = 0; b < 4; b++) acc[a][b] = make_float4(0.f, 0.f, 0.f, 0.f);

#pragma unroll 1
    for (int ch = 0; ch < IN_F / KC; ch++) {
        __syncthreads();
        // x tile: 256 rows x 32 floats = 2048 float4, 8 per thread
#pragma unroll
        for (int j = 0; j < 8; j++) {
            int i = tid + 256 * j;
            int row = i >> 3;
            int kk = (i & 7) * 4;
            int grow = base + row;
            float4 v = make_float4(0.f, 0.f, 0.f, 0.f);
            if (grow < n) v = *(const float4*)(x + (size_t)grow * IN_F + ch * KC + kk);
            float* p = xs + row * (KC + 1) + kk;
            p[0] = v.x; p[1] = v.y; p[2] = v.z; p[3] = v.w;
        }
        // W chunk: 32 k x 16 float4 = 512, 2 per thread
#pragma unroll
        for (int j = 0; j < 2; j++) {
            int i = tid + 256 * j;
            int kk = i >> 4, c4 = i & 15;
            Wc[kk * 16 + c4] = *(const float4*)(W + (size_t)(ch * KC + kk) * HF + c4 * 4);
        }
        __syncthreads();

#pragma unroll
        for (int k = 0; k < KC; k++) {
            float xv[4];
#pragma unroll
            for (int ri = 0; ri < 4; ri++) xv[ri] = xs[(rq * 4 + ri) * (KC + 1) + k];
            float4 wv[4];
#pragma unroll
            for (int c4 = 0; c4 < 4; c4++) wv[c4] = Wc[k * 16 + head * 4 + c4];
#pragma unroll
            for (int ri = 0; ri < 4; ri++)
#pragma unroll
                for (int c4 = 0; c4 < 4; c4++) {
                    acc[ri][c4].x += xv[ri] * wv[c4].x;
                    acc[ri][c4].y += xv[ri] * wv[c4].y;
                    acc[ri][c4].z += xv[ri] * wv[c4].z;
                    acc[ri][c4].w += xv[ri] * wv[c4].w;
                }
        }
    }

    // epilogue: write h, compute per-node attention scores for this head
    float as[16], at[16];
#pragma unroll
    for (int c = 0; c < 16; c++) {
        as[c] = __ldg(a_src + head * 16 + c);
        at[c] = __ldg(a_tgt + head * 16 + c);
    }
#pragma unroll
    for (int ri = 0; ri < 4; ri++) {
        int row = base + rq * 4 + ri;
        if (row < n) {
            float4* hp = (float4*)(g_h + (size_t)row * HF + head * 16);
            const float* hv = (const float*)&acc[ri][0];
            float ss = 0.f, st = 0.f;
#pragma unroll
            for (int c4 = 0; c4 < 4; c4++) hp[c4] = acc[ri][c4];
#pragma unroll
            for (int c = 0; c < 16; c++) { ss += hv[c] * as[c]; st += hv[c] * at[c]; }
            g_ssrc[row * 4 + head] = ss;
            g_stgt[row * 4 + head] = st;
        }
    }
}

// ---- K2: global max of leaky-relu'd logits (lrelu is monotonic -> apply once) ----
__global__ __launch_bounds__(256) void k_max(
    const int* __restrict__ src, const int* __restrict__ tgt, int e)
{
    const float4* S = (const float4*)g_ssrc;
    const float4* T = (const float4*)g_stgt;
    float m = __int_as_float(0xff800000);
    for (int i = blockIdx.x * blockDim.x + threadIdx.x; i < e;
         i += gridDim.x * blockDim.x) {
        int s = src[i], t = tgt[i];
        float4 a = S[s], b = T[t];
        float e0 = a.x + b.x, e1 = a.y + b.y, e2 = a.z + b.z, e3 = a.w + b.w;
        m = fmaxf(m, fmaxf(fmaxf(e0, e1), fmaxf(e2, e3)));
    }
#pragma unroll
    for (int o = 16; o; o >>= 1) m = fmaxf(m, __shfl_xor_sync(0xffffffffu, m, o));
    __shared__ float red[8];
    int lane = threadIdx.x & 31, w = threadIdx.x >> 5;
    if (lane == 0) red[w] = m;
    __syncthreads();
    if (threadIdx.x == 0) {
        float mm = red[0];
#pragma unroll
        for (int i = 1; i < 8; i++) mm = fmaxf(mm, red[i]);
        mm = mm > 0.f ? mm : 0.2f * mm;   // leaky-relu after max (monotonic)
        atomicMaxFloat(&g_gmax, mm);
    }
}

// ---- K3: denom[tgt,h] += exp(lrelu(e) - gmax) ----
__global__ __launch_bounds__(256) void k_denom(
    const int* __restrict__ src, const int* __restrict__ tgt, int e)
{
    const float4* S = (const float4*)g_ssrc;
    const float4* T = (const float4*)g_stgt;
    const float gm = g_gmax;
    for (int i = blockIdx.x * blockDim.x + threadIdx.x; i < e;
         i += gridDim.x * blockDim.x) {
        int s = src[i], t = tgt[i];
        float4 a = S[s], b = T[t];
        float e0 = a.x + b.x, e1 = a.y + b.y, e2 = a.z + b.z, e3 = a.w + b.w;
        e0 = e0 > 0.f ? e0 : 0.2f * e0;
        e1 = e1 > 0.f ? e1 : 0.2f * e1;
        e2 = e2 > 0.f ? e2 : 0.2f * e2;
        e3 = e3 > 0.f ? e3 : 0.2f * e3;
        float* d = g_denom + (size_t)t * 4;
        atomicAdd(d + 0, __expf(e0 - gm));
        atomicAdd(d + 1, __expf(e1 - gm));
        atomicAdd(d + 2, __expf(e2 - gm));
        atomicAdd(d + 3, __expf(e3 - gm));
    }
}

// ---- K4: out = h * denom/(denom+1e-16) + bias ----
__global__ __launch_bounds__(256) void k_out(
    const float* __restrict__ bias, float* __restrict__ out, int n)
{
    int i = blockIdx.x * blockDim.x + threadIdx.x;   // float4 index, n*16 total
    if (i < n * 16) {
        int node = i >> 4;
        int h = (i >> 2) & 3;
        float d = g_denom[node * 4 + h];
        float r = d / (d + 1e-16f);
        float4 hv = ((const float4*)g_h)[i];
        float4 bv = __ldg((const float4*)bias + (i & 15));
        float4 o;
        o.x = hv.x * r + bv.x;
        o.y = hv.y * r + bv.y;
        o.z = hv.z * r + bv.z;
        o.w = hv.w * r + bv.w;
        ((float4*)out)[i] = o;
    }
}

extern "C" void kernel_launch(void* const* d_in, const int* in_sizes, int n_in,
                              void* d_out, int out_size)
{
    const float* x     = (const float*)d_in[0];
    const int*   ei    = (const int*)d_in[1];
    const float* W     = (const float*)d_in[2];
    const float* a_src = (const float*)d_in[3];
    const float* a_tgt = (const float*)d_in[4];
    const float* bias  = (const float*)d_in[5];
    float* out = (float*)d_out;

    const int n = in_sizes[0] / IN_F;   // 50000
    const int e = in_sizes[1] / 2;      // 800000
    const int* src = ei;
    const int* tgt = ei + e;

    k_init<<<(n * HEADS + 255) / 256, 256>>>(n);
    k_gemm<<<(n + RB - 1) / RB, 256>>>(x, W, a_src, a_tgt, n);
    k_max<<<1024, 256>>>(src, tgt, e);
    k_denom<<<1024, 256>>>(src, tgt, e);
    k_out<<<(n * 16 + 255) / 256, 256>>>(bias, out, n);
}

// round 2
// speedup vs baseline: 1.1279x; 1.1279x over previous
#include <cuda_runtime.h>

#define IN_F 128
#define HF 64          // HEADS*OUT_F
#define KC 32          // k chunk
#define RB 128         // rows per GEMM block

typedef unsigned long long ull;

// ---- scratch: in-degree flags (allocation-free device global) ----
__device__ __align__(16) unsigned char g_deg[50176];   // >= NN, 16B multiple

__device__ __forceinline__ ull ffma2(ull a, ull b, ull c) {
    ull d;
    asm("fma.rn.f32x2 %0, %1, %2, %3;" : "=l"(d) : "l"(a), "l"(b), "l"(c));
    return d;
}
__device__ __forceinline__ ull pack2(float lo, float hi) {
    ull d;
    asm("mov.b64 %0, {%1, %2};" : "=l"(d) : "f"(lo), "f"(hi));
    return d;
}
__device__ __forceinline__ float2 unpack2(ull v) {
    float2 r;
    asm("mov.b64 {%0, %1}, %2;" : "=f"(r.x), "=f"(r.y) : "l"(v));
    return r;
}

// ---- K0: zero the flag array (50176 B = 3136 uint4) ----
__global__ void k_init(int n16) {
    int i = blockIdx.x * blockDim.x + threadIdx.x;
    if (i < n16) ((uint4*)g_deg)[i] = make_uint4(0u, 0u, 0u, 0u);
}

// ---- K1: mark nodes with >=1 incoming edge (idempotent plain stores) ----
__global__ __launch_bounds__(256) void k_mark(const int* __restrict__ tgt, int e) {
    int i = blockIdx.x * blockDim.x + threadIdx.x;
    int e4 = e >> 2;
    if (i < e4) {
        int4 t = ((const int4*)tgt)[i];
        g_deg[t.x] = 1; g_deg[t.y] = 1; g_deg[t.z] = 1; g_deg[t.w] = 1;
    }
    if (i == e4 && (e & 3)) {
        for (int j = e4 * 4; j < e; j++) g_deg[tgt[j]] = 1;
    }
}

// ---- K2: out = (x @ W) * flag + bias,  via packed f32x2 FMA ----
// 256 threads, 128 rows/block. thread = (ry = tid>>2 : 2-row group, head = tid&3).
// Each thread: 2 rows x 16 cols (one head) = 16 f32x2 accumulators.
__global__ __launch_bounds__(256) void k_gemm(
    const float* __restrict__ x, const float* __restrict__ W,
    const float* __restrict__ bias, float* __restrict__ out, int n)
{
    __shared__ float xs[RB * (KC + 1)];            // padded stride 33: conflict-free
    __shared__ __align__(16) float Wc[KC * HF];    // W chunk [k][64]

    const int tid  = threadIdx.x;
    const int base = blockIdx.x * RB;
    const int ry   = tid >> 2;
    const int head = tid & 3;

    ull acc[2][8];
#pragma unroll
    for (int rr = 0; rr < 2; rr++)
#pragma unroll
        for (int j = 0; j < 8; j++) acc[rr][j] = 0ull;   // (+0.f, +0.f)

#pragma unroll 1
    for (int ch = 0; ch < IN_F / KC; ch++) {
        __syncthreads();
        // x tile: 128 rows x 32 floats = 1024 float4, 4 per thread
#pragma unroll
        for (int j = 0; j < 4; j++) {
            int i   = tid + 256 * j;
            int row = i >> 3;
            int kk  = (i & 7) * 4;
            int grow = base + row;
            float4 v = make_float4(0.f, 0.f, 0.f, 0.f);
            if (grow < n) v = *(const float4*)(x + (size_t)grow * IN_F + ch * KC + kk);
            float* p = xs + row * (KC + 1) + kk;
            p[0] = v.x; p[1] = v.y; p[2] = v.z; p[3] = v.w;
        }
        // W chunk: 32 k x 64 cols = 512 float4, 2 per thread (row-major, layout preserved)
#pragma unroll
        for (int j = 0; j < 2; j++) {
            int i = tid + 256 * j;
            ((float4*)Wc)[i] = ((const float4*)(W + (size_t)ch * KC * HF))[i];
        }
        __syncthreads();

#pragma unroll
        for (int k = 0; k < KC; k++) {
            float x0 = xs[(ry * 2 + 0) * (KC + 1) + k];
            float x1 = xs[(ry * 2 + 1) * (KC + 1) + k];
            ull xp0 = pack2(x0, x0);
            ull xp1 = pack2(x1, x1);
            const float* wrow = Wc + k * HF + head * 16;
#pragma unroll
            for (int q = 0; q < 4; q++) {
                ulonglong2 wp = *(const ulonglong2*)(wrow + q * 4);
                acc[0][q * 2 + 0] = ffma2(xp0, wp.x, acc[0][q * 2 + 0]);
                acc[0][q * 2 + 1] = ffma2(xp0, wp.y, acc[0][q * 2 + 1]);
                acc[1][q * 2 + 0] = ffma2(xp1, wp.x, acc[1][q * 2 + 0]);
                acc[1][q * 2 + 1] = ffma2(xp1, wp.y, acc[1][q * 2 + 1]);
            }
        }
    }

    // epilogue: out = h * (indegree>0) + bias
    float4 bv[4];
#pragma unroll
    for (int q = 0; q < 4; q++) bv[q] = __ldg((const float4*)bias + head * 4 + q);

#pragma unroll
    for (int rr = 0; rr < 2; rr++) {
        int row = base + ry * 2 + rr;
        if (row < n) {
            float r = g_deg[row] ? 1.0f : 0.0f;
            float4* op = (float4*)(out + (size_t)row * HF + head * 16);
#pragma unroll
            for (int q = 0; q < 4; q++) {
                float2 a = unpack2(acc[rr][q * 2 + 0]);
                float2 b = unpack2(acc[rr][q * 2 + 1]);
                float4 o;
                o.x = a.x * r + bv[q].x;
                o.y = a.y * r + bv[q].y;
                o.z = b.x * r + bv[q].z;
                o.w = b.y * r + bv[q].w;
                op[q] = o;
            }
        }
    }
}

extern "C" void kernel_launch(void* const* d_in, const int* in_sizes, int n_in,
                              void* d_out, int out_size)
{
    const float* x    = (const float*)d_in[0];
    const int*   ei   = (const int*)d_in[1];
    const float* W    = (const float*)d_in[2];
    const float* bias = (const float*)d_in[5];
    float* out = (float*)d_out;

    const int n = in_sizes[0] / IN_F;   // 50000
    const int e = in_sizes[1] / 2;      // 800000
    const int* tgt = ei + e;

    k_init<<<(3136 + 255) / 256, 256>>>(3136);
    k_mark<<<(e / 4 + 256) / 256, 256>>>(tgt, e);
    k_gemm<<<(n + RB - 1) / RB, 256>>>(x, W, bias, out, n);
}

// round 3
// speedup vs baseline: 1.2239x; 1.0851x over previous
#include <cuda_runtime.h>

#define IN_F 128
#define HF 64          // HEADS*OUT_F
#define KC 32          // k chunk
#define RB 128         // rows per GEMM block
#define NCHUNK (IN_F / KC)

typedef unsigned long long ull;

// ---- scratch: in-degree flags as WORDS (no byte-masked RMW) ----
__device__ __align__(16) int g_flag[50048];   // >= NN, 16B multiple (200 KB)

__device__ __forceinline__ ull ffma2(ull a, ull b, ull c) {
    ull d;
    asm("fma.rn.f32x2 %0, %1, %2, %3;" : "=l"(d) : "l"(a), "l"(b), "l"(c));
    return d;
}
__device__ __forceinline__ ull pack2(float lo, float hi) {
    ull d;
    asm("mov.b64 %0, {%1, %2};" : "=l"(d) : "f"(lo), "f"(hi));
    return d;
}
__device__ __forceinline__ float2 unpack2(ull v) {
    float2 r;
    asm("mov.b64 {%0, %1}, %2;" : "=f"(r.x), "=f"(r.y) : "l"(v));
    return r;
}

// ---- K1: mark nodes with >=1 incoming edge (idempotent word stores) ----
__global__ __launch_bounds__(256) void k_mark(const int* __restrict__ tgt, int e) {
    int i = blockIdx.x * blockDim.x + threadIdx.x;
    int e4 = e >> 2;
    if (i < e4) {
        int4 t = ((const int4*)tgt)[i];
        g_flag[t.x] = 1; g_flag[t.y] = 1; g_flag[t.z] = 1; g_flag[t.w] = 1;
    }
    if (i == e4 && (e & 3)) {
        for (int j = e4 * 4; j < e; j++) g_flag[tgt[j]] = 1;
    }
}

// ---- K2: out = (x @ W) * flag + bias, software-pipelined, f32x2 FMA ----
// 256 threads, 128 rows/block. thread = (ry = tid>>2 : 2-row group, head = tid&3).
__global__ __launch_bounds__(256) void k_gemm(
    const float* __restrict__ x, const float* __restrict__ W,
    const float* __restrict__ bias, float* __restrict__ out, int n)
{
    __shared__ float xs[RB * (KC + 1)];            // padded stride 33: conflict-free
    __shared__ __align__(16) float Wc[KC * HF];    // W chunk [k][64]

    const int tid  = threadIdx.x;
    const int base = blockIdx.x * RB;
    const int ry   = tid >> 2;
    const int head = tid & 3;

    // staging-geometry for this thread (x tile: 1024 float4, 4 per thread)
    int srow[4], skk[4];
#pragma unroll
    for (int j = 0; j < 4; j++) {
        int i = tid + 256 * j;
        srow[j] = i >> 3;
        skk[j]  = (i & 7) * 4;
    }

    ull acc[2][8];
#pragma unroll
    for (int rr = 0; rr < 2; rr++)
#pragma unroll
        for (int j = 0; j < 8; j++) acc[rr][j] = 0ull;

    float4 xreg[4];
    float4 wreg[2];

    // prologue: fetch chunk 0 into regs, stage to smem
#pragma unroll
    for (int j = 0; j < 4; j++) {
        int grow = base + srow[j];
        xreg[j] = make_float4(0.f, 0.f, 0.f, 0.f);
        if (grow < n) xreg[j] = *(const float4*)(x + (size_t)grow * IN_F + skk[j]);
    }
#pragma unroll
    for (int j = 0; j < 2; j++)
        wreg[j] = ((const float4*)W)[tid + 256 * j];

#pragma unroll
    for (int j = 0; j < 4; j++) {
        float* p = xs + srow[j] * (KC + 1) + skk[j];
        p[0] = xreg[j].x; p[1] = xreg[j].y; p[2] = xreg[j].z; p[3] = xreg[j].w;
    }
#pragma unroll
    for (int j = 0; j < 2; j++)
        ((float4*)Wc)[tid + 256 * j] = wreg[j];
    __syncthreads();

#pragma unroll
    for (int ch = 0; ch < NCHUNK; ch++) {
        // prefetch chunk ch+1 while computing chunk ch
        if (ch + 1 < NCHUNK) {
#pragma unroll
            for (int j = 0; j < 4; j++) {
                int grow = base + srow[j];
                xreg[j] = make_float4(0.f, 0.f, 0.f, 0.f);
                if (grow < n)
                    xreg[j] = *(const float4*)(x + (size_t)grow * IN_F + (ch + 1) * KC + skk[j]);
            }
#pragma unroll
            for (int j = 0; j < 2; j++)
                wreg[j] = ((const float4*)(W + (size_t)(ch + 1) * KC * HF))[tid + 256 * j];
        }

#pragma unroll
        for (int k = 0; k < KC; k++) {
            float x0 = xs[(ry * 2 + 0) * (KC + 1) + k];
            float x1 = xs[(ry * 2 + 1) * (KC + 1) + k];
            ull xp0 = pack2(x0, x0);
            ull xp1 = pack2(x1, x1);
            const float* wrow = Wc + k * HF + head * 16;
#pragma unroll
            for (int q = 0; q < 4; q++) {
                ulonglong2 wp = *(const ulonglong2*)(wrow + q * 4);
                acc[0][q * 2 + 0] = ffma2(xp0, wp.x, acc[0][q * 2 + 0]);
                acc[0][q * 2 + 1] = ffma2(xp0, wp.y, acc[0][q * 2 + 1]);
                acc[1][q * 2 + 0] = ffma2(xp1, wp.x, acc[1][q * 2 + 0]);
                acc[1][q * 2 + 1] = ffma2(xp1, wp.y, acc[1][q * 2 + 1]);
            }
        }
        __syncthreads();

        if (ch + 1 < NCHUNK) {
#pragma unroll
            for (int j = 0; j < 4; j++) {
                float* p = xs + srow[j] * (KC + 1) + skk[j];
                p[0] = xreg[j].x; p[1] = xreg[j].y; p[2] = xreg[j].z; p[3] = xreg[j].w;
            }
#pragma unroll
            for (int j = 0; j < 2; j++)
                ((float4*)Wc)[tid + 256 * j] = wreg[j];
            __syncthreads();
        }
    }

    // epilogue: out = h * (indegree>0) + bias
    float4 bv[4];
#pragma unroll
    for (int q = 0; q < 4; q++) bv[q] = __ldg((const float4*)bias + head * 4 + q);

#pragma unroll
    for (int rr = 0; rr < 2; rr++) {
        int row = base + ry * 2 + rr;
        if (row < n) {
            float r = g_flag[row] ? 1.0f : 0.0f;
            float4* op = (float4*)(out + (size_t)row * HF + head * 16);
#pragma unroll
            for (int q = 0; q < 4; q++) {
                float2 a = unpack2(acc[rr][q * 2 + 0]);
                float2 b = unpack2(acc[rr][q * 2 + 1]);
                float4 o;
                o.x = a.x * r + bv[q].x;
                o.y = a.y * r + bv[q].y;
                o.z = b.x * r + bv[q].z;
                o.w = b.y * r + bv[q].w;
                op[q] = o;
            }
        }
    }
}

extern "C" void kernel_launch(void* const* d_in, const int* in_sizes, int n_in,
                              void* d_out, int out_size)
{
    const float* x    = (const float*)d_in[0];
    const int*   ei   = (const int*)d_in[1];
    const float* W    = (const float*)d_in[2];
    const float* bias = (const float*)d_in[5];
    float* out = (float*)d_out;

    const int n = in_sizes[0] / IN_F;   // 50000
    const int e = in_sizes[1] / 2;      // 800000
    const int* tgt = ei + e;

    void* flag_ptr = nullptr;
    cudaGetSymbolAddress(&flag_ptr, g_flag);
    cudaMemsetAsync(flag_ptr, 0, sizeof(g_flag), 0);

    k_mark<<<(e / 4 + 255) / 256, 256>>>(tgt, e);
    k_gemm<<<(n + RB - 1) / RB, 256>>>(x, W, bias, out, n);
}

// round 4
// speedup vs baseline: 2.3630x; 1.9307x over previous
#include <cuda_runtime.h>

#define IN_F 128
#define HF 64          // HEADS*OUT_F
#define RB 128         // rows per block
#define NT 128         // threads per block

typedef unsigned long long ull;

// ---- scratch: in-degree flags as words ----
__device__ __align__(16) int g_flag[50048];

__device__ __forceinline__ ull ffma2(ull a, ull b, ull c) {
    ull d;
    asm("fma.rn.f32x2 %0, %1, %2, %3;" : "=l"(d) : "l"(a), "l"(b), "l"(c));
    return d;
}
__device__ __forceinline__ ull pack2(float lo, float hi) {
    ull d;
    asm("mov.b64 %0, {%1, %2};" : "=l"(d) : "f"(lo), "f"(hi));
    return d;
}
__device__ __forceinline__ float2 unpack2(ull v) {
    float2 r;
    asm("mov.b64 {%0, %1}, %2;" : "=f"(r.x), "=f"(r.y) : "l"(v));
    return r;
}

// ---- K1: mark nodes with >=1 incoming edge (idempotent word stores) ----
__global__ __launch_bounds__(256) void k_mark(const int* __restrict__ tgt, int e) {
    int i = blockIdx.x * blockDim.x + threadIdx.x;
    int e4 = e >> 2;
    if (i < e4) {
        int4 t = ((const int4*)tgt)[i];
        g_flag[t.x] = 1; g_flag[t.y] = 1; g_flag[t.z] = 1; g_flag[t.w] = 1;
    }
    if (i == e4 && (e & 3)) {
        for (int j = e4 * 4; j < e; j++) g_flag[tgt[j]] = 1;
    }
}

// ---- K2: out = (x @ W) * flag + bias ----
// 128 threads. thread = (rg = tid>>3 : 8-row group, cg = tid&7 : 8-col group).
// x streamed from global (registers, double-buffered); W staged once in smem,
// interleaved [k][half][cg] so warp LDS.128 is 128B contiguous (conflict-free).
__global__ __launch_bounds__(NT, 3) void k_gemm(
    const float* __restrict__ x, const float* __restrict__ W,
    const float* __restrict__ bias, float* __restrict__ out, int n)
{
    __shared__ __align__(16) float Ws[IN_F * HF];   // 32 KB, interleaved layout

    const int tid = threadIdx.x;
    const int cg  = tid & 7;
    const int rg  = tid >> 3;
    const int base_row = blockIdx.x * RB + rg * 8;

    // ---- stage W: entry e <-> (k = e>>4, half = (e>>3)&1, cg = e&7) ----
    // Ws[e] (float4) = W[k][ (e&7)*8 + ((e>>3)&1)*4 .. +3 ]  -> lanes read a full
    // 256B row of W contiguously (coalesced), store sequentially (no conflicts).
#pragma unroll
    for (int j = 0; j < 16; j++) {
        int e = tid + NT * j;
        int k = e >> 4;
        int c = (e & 7) * 8 + ((e >> 3) & 1) * 4;
        ((float4*)Ws)[e] = *(const float4*)(W + (size_t)k * HF + c);
    }
    __syncthreads();

    // clamped row pointers (last block has rows >= n; loads stay in-bounds, unused)
    const float* xrow[8];
#pragma unroll
    for (int r = 0; r < 8; r++) {
        int row = base_row + r;
        row = row < n ? row : n - 1;
        xrow[r] = x + (size_t)row * IN_F;
    }

    ull acc[8][4];
#pragma unroll
    for (int r = 0; r < 8; r++)
#pragma unroll
        for (int c = 0; c < 4; c++) acc[r][c] = 0ull;

    const ulonglong2* wsp = (const ulonglong2*)Ws;

    float4 xa[8], xb[8];
#pragma unroll
    for (int r = 0; r < 8; r++) xa[r] = *(const float4*)(xrow[r]);

#define COMPUTE4(XR, KBASE)                                                   \
    do {                                                                      \
        _Pragma("unroll")                                                     \
        for (int i = 0; i < 4; i++) {                                         \
            const int k = (KBASE) + i;                                        \
            ulonglong2 wa = wsp[k * 16 + cg];                                 \
            ulonglong2 wb = wsp[k * 16 + 8 + cg];                             \
            _Pragma("unroll")                                                 \
            for (int r = 0; r < 8; r++) {                                     \
                float xv = (i == 0) ? XR[r].x : (i == 1) ? XR[r].y            \
                         : (i == 2) ? XR[r].z : XR[r].w;                      \
                ull xd = pack2(xv, xv);                                       \
                acc[r][0] = ffma2(xd, wa.x, acc[r][0]);                       \
                acc[r][1] = ffma2(xd, wa.y, acc[r][1]);                       \
                acc[r][2] = ffma2(xd, wb.x, acc[r][2]);                       \
                acc[r][3] = ffma2(xd, wb.y, acc[r][3]);                       \
            }                                                                 \
        }                                                                     \
    } while (0)

#pragma unroll 1
    for (int kb2 = 0; kb2 < 16; kb2++) {
        const int kA = kb2 * 8;
        // prefetch block B (k = kA+4..kA+7)
#pragma unroll
        for (int r = 0; r < 8; r++)
            xb[r] = *(const float4*)(xrow[r] + kA + 4);
        COMPUTE4(xa, kA);
        // prefetch next block A (k = kA+8..; harmless reload of 0 on last iter)
        const int nxt = (kb2 == 15) ? 0 : kA + 8;
#pragma unroll
        for (int r = 0; r < 8; r++)
            xa[r] = *(const float4*)(xrow[r] + nxt);
        COMPUTE4(xb, kA + 4);
    }
#undef COMPUTE4

    // ---- epilogue: out = h * (indegree>0) + bias ----
    float4 b0 = __ldg((const float4*)(bias + cg * 8));
    float4 b1 = __ldg((const float4*)(bias + cg * 8 + 4));

#pragma unroll
    for (int r = 0; r < 8; r++) {
        int row = base_row + r;
        if (row < n) {
            float s = g_flag[row] ? 1.0f : 0.0f;
            float2 a0 = unpack2(acc[r][0]);
            float2 a1 = unpack2(acc[r][1]);
            float2 a2 = unpack2(acc[r][2]);
            float2 a3 = unpack2(acc[r][3]);
            float4 o0, o1;
            o0.x = a0.x * s + b0.x;  o0.y = a0.y * s + b0.y;
            o0.z = a1.x * s + b0.z;  o0.w = a1.y * s + b0.w;
            o1.x = a2.x * s + b1.x;  o1.y = a2.y * s + b1.y;
            o1.z = a3.x * s + b1.z;  o1.w = a3.y * s + b1.w;
            float* op = out + (size_t)row * HF + cg * 8;
            *(float4*)op       = o0;
            *(float4*)(op + 4) = o1;
        }
    }
}

extern "C" void kernel_launch(void* const* d_in, const int* in_sizes, int n_in,
                              void* d_out, int out_size)
{
    const float* x    = (const float*)d_in[0];
    const int*   ei   = (const int*)d_in[1];
    const float* W    = (const float*)d_in[2];
    const float* bias = (const float*)d_in[5];
    float* out = (float*)d_out;

    const int n = in_sizes[0] / IN_F;   // 50000
    const int e = in_sizes[1] / 2;      // 800000
    const int* tgt = ei + e;

    void* flag_ptr = nullptr;
    cudaGetSymbolAddress(&flag_ptr, g_flag);
    cudaMemsetAsync(flag_ptr, 0, sizeof(g_flag), 0);

    k_mark<<<(e / 4 + 255) / 256, 256>>>(tgt, e);
    k_gemm<<<(n + RB - 1) / RB, 256 / 2>>>(x, W, bias, out, n);
}